// round 11
// baseline (speedup 1.0000x reference)
#include <cuda_runtime.h>

// LoRALayerNorm: x [B=2, S=4096, N=8192] fp32 — ONE kernel, oversubscribed
// 8192-CTA grid (wave load-balancing beats persistent layouts on B300).
// CTAs 0..15 (wave-1 residents, scheduled first) compute the rank-4 diag
// scale/shift vectors into device globals after issuing their own x loads.
// Every CTA issues its x loads FIRST, then spins on a 16-producer ready
// counter: the spin overlaps in-flight DRAM loads for wave-1 CTAs and is a
// single satisfied L2 read for later waves.
//
// R10 lesson: the epilogue MUST read g_scale/g_shift with coherent loads
// (__ldcg). __ldg's read-only contract let ptxas hoist the loads above the
// spin barrier -> stale zeros on early CTAs (rel_err 0.11).

#define N_FEAT 8192
#define N_ROWS 8192
#define RANK 4
#define SCALING_F 2.0f   // ALPHA/RANK = 8/4
#define EPS_F 1e-5f

#define TPB 512
#define VPT 4            // float4 per thread: 512*4*4 = 8192 floats per row
#define N_PROD 16        // producer CTAs: 16*512 threads = 8192 features

__device__ float g_scale[N_FEAT];
__device__ float g_shift[N_FEAT];
__device__ unsigned int g_ready = 0;   // producers arrived (0..16)
__device__ unsigned int g_done = 0;    // CTAs finished (reset mechanism)

__global__ __launch_bounds__(TPB, 3)
void lora_layernorm_fused_kernel(const float* __restrict__ x,
                                 const float* __restrict__ sA,
                                 const float* __restrict__ sB,
                                 const float* __restrict__ hA,
                                 const float* __restrict__ hB,
                                 float* __restrict__ out) {
    const int row = blockIdx.x;
    const int tid = threadIdx.x;
    const int wid = tid >> 5;
    const int lane = tid & 31;
    const float4* xrow = reinterpret_cast<const float4*>(x + (size_t)row * N_FEAT);
    float4* orow = reinterpret_cast<float4*>(out + (size_t)row * N_FEAT);

    // Issue this CTA's x loads first — they stay in flight through phase 0 /
    // the flag spin / the reduction.
    float4 v[VPT];
#pragma unroll
    for (int k = 0; k < VPT; k++) {
        v[k] = __ldcs(&xrow[tid + k * TPB]);
    }

    // ---- Phase 0 (producer CTAs only): sc/sh vectors, one feature/thread ----
    if (blockIdx.x < N_PROD) {
        const int i = blockIdx.x * TPB + tid;
        float4 a_s = __ldg(reinterpret_cast<const float4*>(sA + i * RANK));
        float4 a_h = __ldg(reinterpret_cast<const float4*>(hA + i * RANK));
        float sc = a_s.x * __ldg(&sB[0 * N_FEAT + i])
                 + a_s.y * __ldg(&sB[1 * N_FEAT + i])
                 + a_s.z * __ldg(&sB[2 * N_FEAT + i])
                 + a_s.w * __ldg(&sB[3 * N_FEAT + i]);
        float sh = a_h.x * __ldg(&hB[0 * N_FEAT + i])
                 + a_h.y * __ldg(&hB[1 * N_FEAT + i])
                 + a_h.z * __ldg(&hB[2 * N_FEAT + i])
                 + a_h.w * __ldg(&hB[3 * N_FEAT + i]);
        g_scale[i] = sc * SCALING_F;
        g_shift[i] = sh * SCALING_F;
        __threadfence();                 // release the vector writes
        __syncthreads();                 // all 512 features of this CTA done
        if (tid == 0) atomicAdd(&g_ready, 1u);
    }

    // ---- Reduction (overlaps the producers' phase 0) ----
    float sum = 0.0f, sumsq = 0.0f;
#pragma unroll
    for (int k = 0; k < VPT; k++) {
        float4 t = v[k];
        sum += t.x + t.y + t.z + t.w;
        sumsq += t.x * t.x + t.y * t.y + t.z * t.z + t.w * t.w;
    }
#pragma unroll
    for (int off = 16; off > 0; off >>= 1) {
        sum += __shfl_xor_sync(0xffffffffu, sum, off);
        sumsq += __shfl_xor_sync(0xffffffffu, sumsq, off);
    }

    __shared__ float s_sum[TPB / 32];
    __shared__ float s_sumsq[TPB / 32];
    __shared__ float s_mean, s_rstd;
    if (lane == 0) {
        s_sum[wid] = sum;
        s_sumsq[wid] = sumsq;
    }
    __syncthreads();
    if (wid == 0) {
        float a = (lane < TPB / 32) ? s_sum[lane] : 0.0f;
        float b = (lane < TPB / 32) ? s_sumsq[lane] : 0.0f;
#pragma unroll
        for (int off = 8; off > 0; off >>= 1) {
            a += __shfl_xor_sync(0xffffffffu, a, off);
            b += __shfl_xor_sync(0xffffffffu, b, off);
        }
        if (lane == 0) {
            float mean = a * (1.0f / N_FEAT);
            float var = b * (1.0f / N_FEAT) - mean * mean;
            s_mean = mean;
            s_rstd = rsqrtf(var + EPS_F);
        }
    }

    // ---- Wait for all 16 producers (tid 0 spins; usually already done) ----
    if (tid == 0) {
        while (*(volatile unsigned int*)&g_ready < N_PROD) { }
        __threadfence();                 // acquire before reading g_scale/shift
    }
    __syncthreads();
    const float mean = s_mean;
    const float rstd = s_rstd;

    // ---- Epilogue: COHERENT (.cg) loads of the freshly-produced vectors ----
    const float4* scv = reinterpret_cast<const float4*>(g_scale);
    const float4* shv = reinterpret_cast<const float4*>(g_shift);
#pragma unroll
    for (int k = 0; k < VPT; k++) {
        const int idx = tid + k * TPB;
        float4 sc = __ldcg(&scv[idx]);
        float4 sh = __ldcg(&shv[idx]);
        float4 t = v[k];
        float4 o;
        o.x = (t.x - mean) * rstd * sc.x + sh.x;
        o.y = (t.y - mean) * rstd * sc.y + sh.y;
        o.z = (t.z - mean) * rstd * sc.z + sh.z;
        o.w = (t.w - mean) * rstd * sc.w + sh.w;
        __stcs(&orow[idx], o);
    }

    // ---- Replay-safe reset: the LAST CTA to finish zeroes the flags.
    // Every other CTA has already passed its spin (g_done is incremented
    // after the epilogue), so no thread of this launch reads g_ready again;
    // the next (serialized) launch starts from a clean state.
    if (tid == 0) {
        unsigned int old = atomicAdd(&g_done, 1u);
        if (old == N_ROWS - 1) {
            atomicExch(&g_done, 0u);
            atomicExch(&g_ready, 0u);
        }
    }
}

// ---------------------------------------------------------------------------
extern "C" void kernel_launch(void* const* d_in, const int* in_sizes, int n_in,
                              void* d_out, int out_size) {
    const float* x = (const float*)d_in[0];
    const float* sA = (const float*)d_in[1];
    const float* sB = (const float*)d_in[2];
    const float* hA = (const float*)d_in[3];
    const float* hB = (const float*)d_in[4];
    float* out = (float*)d_out;

    lora_layernorm_fused_kernel<<<N_ROWS, TPB>>>(x, sA, sB, hA, hB, out);
}